// round 4
// baseline (speedup 1.0000x reference)
#include <cuda_runtime.h>
#include <cuda_bf16.h>

// Problem constants: outputs [64,512,1000] f32, labels [64,512] i32
#define LBL 1000
#define NROWS_MAX 32768
#define PREF_ROWS 24576                 // ~98 MB prefetched into 126 MB L2

__device__ int g_argm[NROWS_MAX];
__device__ __align__(16) int g_first[1024];   // static zero-init; k_scan re-zeros
__device__ __align__(16) int g_idx[1024];     // holds pinv (inverse permutation)

// ---------------------------------------------------------------------------
// K1: per-row argmax (original index space) + first-occurrence.
// First-occurrence encoded as max(N - w) over rows w with label lab, so the
// "empty" state is 0 => no init kernel needed (static zero + scan self-reset).
// One warp per row; 250 float4 per row across 32 lanes (MLP=8).
// __ldcs: evict-first (argmax self-evicts L2 anyway; keeps L2 clean).
// ---------------------------------------------------------------------------
__global__ __launch_bounds__(256) void k_argmax(const float* __restrict__ in,
                                                const int* __restrict__ labels,
                                                int N) {
    int w    = (blockIdx.x * blockDim.x + threadIdx.x) >> 5;
    int lane = threadIdx.x & 31;
    if (w >= N) return;

    const float4* rp = reinterpret_cast<const float4*>(in) + (size_t)w * 250;
    float bv = -3.402823466e38f;
    int   bi = 0;
#pragma unroll
    for (int it = 0; it < 7; ++it) {           // k = lane + 32*it <= 223 < 250
        int k = lane + it * 32;
        float4 v = __ldcs(&rp[k]);
        int b = k * 4;
        if (v.x > bv) { bv = v.x; bi = b;     }
        if (v.y > bv) { bv = v.y; bi = b + 1; }
        if (v.z > bv) { bv = v.z; bi = b + 2; }
        if (v.w > bv) { bv = v.w; bi = b + 3; }
    }
    if (lane < 26) {                            // tail: k = lane + 224 < 250
        int k = lane + 224;
        float4 v = __ldcs(&rp[k]);
        int b = k * 4;
        if (v.x > bv) { bv = v.x; bi = b;     }
        if (v.y > bv) { bv = v.y; bi = b + 1; }
        if (v.z > bv) { bv = v.z; bi = b + 2; }
        if (v.w > bv) { bv = v.w; bi = b + 3; }
    }
#pragma unroll
    for (int off = 16; off > 0; off >>= 1) {
        float ov = __shfl_down_sync(0xFFFFFFFFu, bv, off);
        int   oi = __shfl_down_sync(0xFFFFFFFFu, bi, off);
        if (ov > bv || (ov == bv && oi < bi)) { bv = ov; bi = oi; }
    }
    if (lane == 0) {
        g_argm[w] = bi;
        atomicMax(&g_first[labels[w]], N - w);   // first occurrence = max(N-w)
    }
}

// ---------------------------------------------------------------------------
// K_PF: L2 prefetch of the first PREF_ROWS input rows (runs on a forked
// stream, concurrent with k_scan — fills the otherwise-idle DRAM pipe).
// __ldcg: cache in L2 only. asm sink keeps the loads alive.
// ---------------------------------------------------------------------------
__global__ __launch_bounds__(256) void k_prefetch(const float4* __restrict__ in,
                                                  int nvec) {
    int stride = gridDim.x * blockDim.x;
    float acc = 0.f;
    for (int i = blockIdx.x * blockDim.x + threadIdx.x; i < nvec; i += stride) {
        float4 v = __ldcg(&in[i]);
        acc += v.x + v.y + v.z + v.w;
    }
    asm volatile("" :: "f"(acc));
}

// ---------------------------------------------------------------------------
// K2: single block.
//   Phase A: rank events (first occurrences) by row via 32768-bit bitmap +
//            1024-word popc prefix-sum. Self-resets g_first for next replay.
//   Phase B: serial scan (thread 0) with 1-ahead prefetch of BOTH
//            pinv[m_{e+1}] and pinv[lab_{e+1}], register-patched against the
//            current event's stores.
//   Output: g_idx = pinv directly (gather scatters with pinv).
//
// Event semantics: r = pinv[m]; if (r != lab) swap(pinv[r], pinv[lab]).
// ---------------------------------------------------------------------------
__global__ __launch_bounds__(1024) void k_scan(int N) {
    __shared__ unsigned  sbit[1024];   // 32768-bit row bitmap
    __shared__ int       sexc[1024];   // exclusive popc prefix per word
    __shared__ long long ev[1024];     // packed (m << 32) | lab, sorted by row
    __shared__ int       pinv[1024];
    __shared__ int       wsum[32];
    __shared__ int       sE;

    int t = threadIdx.x;
    int lane = t & 31, w = t >> 5;

    sbit[t] = 0u;
    pinv[t] = t;
    int enc = (t < LBL) ? g_first[t] : 0;
    g_first[t] = 0;                    // reset for next graph replay
    int myf = (enc > 0) ? (N - enc) : -1;
    __syncthreads();

    if (myf >= 0)
        atomicOr(&sbit[myf >> 5], 1u << (myf & 31));
    __syncthreads();

    // block prefix-sum of per-word popcounts
    unsigned word = sbit[t];
    int c = __popc(word);
    int x = c;
#pragma unroll
    for (int o = 1; o < 32; o <<= 1) {
        int y = __shfl_up_sync(0xFFFFFFFFu, x, o);
        if (lane >= o) x += y;
    }
    if (lane == 31) wsum[w] = x;
    __syncthreads();
    if (t < 32) {
        int v = wsum[t];
        int iv = v;
#pragma unroll
        for (int o = 1; o < 32; o <<= 1) {
            int y = __shfl_up_sync(0xFFFFFFFFu, iv, o);
            if (t >= o) iv += y;
        }
        wsum[t] = iv - v;          // exclusive warp offset
        if (t == 31) sE = iv;      // total number of events
    }
    __syncthreads();
    sexc[t] = wsum[w] + (x - c);
    __syncthreads();

    if (myf >= 0) {
        unsigned wv = sbit[myf >> 5];
        int rank = sexc[myf >> 5] + __popc(wv & ((1u << (myf & 31)) - 1u));
        ev[rank] = ((long long)g_argm[myf] << 32) | (unsigned)t;
    }
    __syncthreads();

    // Phase B: serial event loop (thread 0)
    if (t == 0) {
        int E = sE;
        if (E > 0) {
            long long e0 = ev[0];
            int m   = (int)(e0 >> 32);
            int lab = (int)(e0 & 0xFFFFFFFF);
            int r   = pinv[m];
            int pl  = pinv[lab];
            for (int e = 0; e < E; ++e) {
                int pr = pinv[r];
                int m1 = 0, lab1 = 0, nm = 0, nl = 0;
                if (e + 1 < E) {
                    long long e1 = ev[e + 1];
                    m1   = (int)(e1 >> 32);
                    lab1 = (int)(e1 & 0xFFFFFFFF);
                    nm   = pinv[m1];         // issued BEFORE this event's stores
                    nl   = pinv[lab1];
                }
                // branchless swap (r==lab => same-value rewrite, no-op)
                pinv[r]   = pl;
                pinv[lab] = pr;
                // patch both prefetches against this event's two stores
                int rn = nm;
                if (m1 == r)     rn = pl;
                if (m1 == lab)   rn = pr;
                int pln = nl;
                if (lab1 == r)   pln = pl;
                if (lab1 == lab) pln = pr;
                m = m1; lab = lab1; r = rn; pl = pln;
            }
        }
    }
    __syncthreads();

    if (t < LBL) g_idx[t] = pinv[t];   // store pinv directly (scatter gather)
}

// ---------------------------------------------------------------------------
// K3: out[n, pinv[k]] = in[n, k]  (equivalent to out[n,j] = in[n, idx[j]]).
// FORWARD row order: rows 0..PREF_ROWS were just prefetched into L2.
// Stage permuted via scalar STS (issue-only), coalesced float4 LDS,
// streaming float4 STG (__stcs: evict-first, protects prefetched read lines).
// ---------------------------------------------------------------------------
__global__ __launch_bounds__(256) void k_gather(const float* __restrict__ in,
                                                float* __restrict__ out, int N) {
    __shared__ int4  sidx[250];        // pinv, packed
    __shared__ float srow[8][1000];

    int t    = threadIdx.x;
    int wid  = t >> 5;
    int lane = t & 31;

    if (t < 250) sidx[t] = reinterpret_cast<const int4*>(g_idx)[t];

    int row = blockIdx.x * 8 + wid;
    float4 v[8];
    if (row < N) {
        const float4* rp = reinterpret_cast<const float4*>(in + (size_t)row * 1000);
#pragma unroll
        for (int it = 0; it < 8; ++it) {
            int k = lane + it * 32;
            if (k < 250) v[it] = rp[k];
        }
    }
    __syncthreads();   // covers sidx (row loads already in flight)

    if (row < N) {
        float* my = &srow[wid][0];
#pragma unroll
        for (int it = 0; it < 8; ++it) {
            int k = lane + it * 32;
            if (k < 250) {
                int4 p = sidx[k];
                my[p.x] = v[it].x;     // permuted scatter into smem
                my[p.y] = v[it].y;
                my[p.z] = v[it].z;
                my[p.w] = v[it].w;
            }
        }
        __syncwarp();
        float4* op = reinterpret_cast<float4*>(out + (size_t)row * 1000);
        const float4* mv = reinterpret_cast<const float4*>(my);
#pragma unroll
        for (int it = 0; it < 8; ++it) {
            int k = lane + it * 32;
            if (k < 250) __stcs(&op[k], mv[k]);   // coalesced streaming write
        }
    }
}

// ---------------------------------------------------------------------------
extern "C" void kernel_launch(void* const* d_in, const int* in_sizes, int n_in,
                              void* d_out, int out_size) {
    const float* in     = (const float*)d_in[0];
    const int*   labels = (const int*)d_in[1];
    float*       out    = (float*)d_out;
    int N = in_sizes[1];   // 32768 rows; L = 1000

    // lazily-created fork stream + events (host objects only; no device mem)
    static cudaStream_t s2 = nullptr;
    static cudaEvent_t  evFork = nullptr, evJoin = nullptr;
    if (!s2) {
        cudaStreamCreateWithFlags(&s2, cudaStreamNonBlocking);
        cudaEventCreateWithFlags(&evFork, cudaEventDisableTiming);
        cudaEventCreateWithFlags(&evJoin, cudaEventDisableTiming);
    }

    k_argmax<<<(N + 7) / 8, 256>>>(in, labels, N);

    // fork: prefetch input into L2 concurrently with the serial scan
    cudaEventRecord(evFork, 0);
    cudaStreamWaitEvent(s2, evFork, 0);
    int prows = (N < PREF_ROWS) ? N : PREF_ROWS;
    k_prefetch<<<1184, 256, 0, s2>>>(reinterpret_cast<const float4*>(in),
                                     prows * 250);
    cudaEventRecord(evJoin, s2);

    k_scan<<<1, 1024>>>(N);

    // join: gather needs both pinv (scan) and the warmed L2 (prefetch)
    cudaStreamWaitEvent(0, evJoin, 0);
    k_gather<<<(N + 7) / 8, 256>>>(in, out, N);
}

// round 5
// speedup vs baseline: 1.1541x; 1.1541x over previous
#include <cuda_runtime.h>
#include <cuda_bf16.h>

// Problem constants: outputs [64,512,1000] f32, labels [64,512] i32
#define LBL 1000

__device__ __align__(16) int g_first[1024];     // static zero-init; k_scan re-zeros
__device__ __align__(16) int g_argm_ev[1024];   // argmax of each label's first row
__device__ __align__(16) int g_idx[1024];       // pinv (inverse permutation)

// ---------------------------------------------------------------------------
// K0: first occurrence per label, from labels only.
// Encoded as max(N - w) so the empty state is 0 (static zero init, no reset
// kernel; k_scan re-zeros after consuming). 32768 atomics over 1000 addrs.
// ---------------------------------------------------------------------------
__global__ __launch_bounds__(256) void k_first(const int* __restrict__ labels,
                                               int N) {
    int i = blockIdx.x * blockDim.x + threadIdx.x;
    if (i < N) atomicMax(&g_first[labels[i]], N - i);
}

// ---------------------------------------------------------------------------
// K1: argmax of ONLY the first-occurrence rows (<=1000 rows, ~4 MB).
// One warp per label; warp t handles row decode(g_first[t]) if valid.
// Result stored label-indexed in g_argm_ev.
// ---------------------------------------------------------------------------
__global__ __launch_bounds__(256) void k_argmax_ev(const float* __restrict__ in,
                                                   int N) {
    int t    = (blockIdx.x * blockDim.x + threadIdx.x) >> 5;   // label id
    int lane = threadIdx.x & 31;
    if (t >= LBL) return;
    int enc = g_first[t];
    if (enc <= 0) return;            // label never occurs
    int row = N - enc;               // first-occurrence row

    const float4* rp = reinterpret_cast<const float4*>(in) + (size_t)row * 250;
    float bv = -3.402823466e38f;
    int   bi = 0;
#pragma unroll
    for (int it = 0; it < 7; ++it) {             // k = lane + 32*it <= 223
        int k = lane + it * 32;
        float4 v = rp[k];
        int b = k * 4;
        if (v.x > bv) { bv = v.x; bi = b;     }
        if (v.y > bv) { bv = v.y; bi = b + 1; }
        if (v.z > bv) { bv = v.z; bi = b + 2; }
        if (v.w > bv) { bv = v.w; bi = b + 3; }
    }
    if (lane < 26) {                              // tail: k = lane + 224 < 250
        int k = lane + 224;
        float4 v = rp[k];
        int b = k * 4;
        if (v.x > bv) { bv = v.x; bi = b;     }
        if (v.y > bv) { bv = v.y; bi = b + 1; }
        if (v.z > bv) { bv = v.z; bi = b + 2; }
        if (v.w > bv) { bv = v.w; bi = b + 3; }
    }
#pragma unroll
    for (int off = 16; off > 0; off >>= 1) {
        float ov = __shfl_down_sync(0xFFFFFFFFu, bv, off);
        int   oi = __shfl_down_sync(0xFFFFFFFFu, bi, off);
        if (ov > bv || (ov == bv && oi < bi)) { bv = ov; bi = oi; }
    }
    if (lane == 0) g_argm_ev[t] = bi;
}

// ---------------------------------------------------------------------------
// K2: single block.
//   Phase A: rank events (first occurrences) by row via 32768-bit bitmap +
//            1024-word popc prefix-sum. Self-resets g_first for next replay.
//   Phase B: serial scan (thread 0) with 1-ahead prefetch of BOTH
//            pinv[m_{e+1}] and pinv[lab_{e+1}], register-patched against the
//            current event's stores.
//   Output: g_idx = pinv directly (gather scatters with pinv).
//
// Event semantics: r = pinv[m]; if (r != lab) swap(pinv[r], pinv[lab]).
// ---------------------------------------------------------------------------
__global__ __launch_bounds__(1024) void k_scan(int N) {
    __shared__ unsigned  sbit[1024];   // 32768-bit row bitmap
    __shared__ int       sexc[1024];   // exclusive popc prefix per word
    __shared__ long long ev[1024];     // packed (m << 32) | lab, sorted by row
    __shared__ int       pinv[1024];
    __shared__ int       wsum[32];
    __shared__ int       sE;

    int t = threadIdx.x;
    int lane = t & 31, w = t >> 5;

    sbit[t] = 0u;
    pinv[t] = t;
    int enc = (t < LBL) ? g_first[t] : 0;
    g_first[t] = 0;                    // reset for next graph replay
    int myf = (enc > 0) ? (N - enc) : -1;
    __syncthreads();

    if (myf >= 0)
        atomicOr(&sbit[myf >> 5], 1u << (myf & 31));
    __syncthreads();

    // block prefix-sum of per-word popcounts
    unsigned word = sbit[t];
    int c = __popc(word);
    int x = c;
#pragma unroll
    for (int o = 1; o < 32; o <<= 1) {
        int y = __shfl_up_sync(0xFFFFFFFFu, x, o);
        if (lane >= o) x += y;
    }
    if (lane == 31) wsum[w] = x;
    __syncthreads();
    if (t < 32) {
        int v = wsum[t];
        int iv = v;
#pragma unroll
        for (int o = 1; o < 32; o <<= 1) {
            int y = __shfl_up_sync(0xFFFFFFFFu, iv, o);
            if (t >= o) iv += y;
        }
        wsum[t] = iv - v;          // exclusive warp offset
        if (t == 31) sE = iv;      // total number of events
    }
    __syncthreads();
    sexc[t] = wsum[w] + (x - c);
    __syncthreads();

    if (myf >= 0) {
        unsigned wv = sbit[myf >> 5];
        int rank = sexc[myf >> 5] + __popc(wv & ((1u << (myf & 31)) - 1u));
        ev[rank] = ((long long)g_argm_ev[t] << 32) | (unsigned)t;
    }
    __syncthreads();

    // Phase B: serial event loop (thread 0)
    if (t == 0) {
        int E = sE;
        if (E > 0) {
            long long e0 = ev[0];
            int m   = (int)(e0 >> 32);
            int lab = (int)(e0 & 0xFFFFFFFF);
            int r   = pinv[m];
            int pl  = pinv[lab];
            for (int e = 0; e < E; ++e) {
                int pr = pinv[r];
                int m1 = 0, lab1 = 0, nm = 0, nl = 0;
                if (e + 1 < E) {
                    long long e1 = ev[e + 1];
                    m1   = (int)(e1 >> 32);
                    lab1 = (int)(e1 & 0xFFFFFFFF);
                    nm   = pinv[m1];         // issued BEFORE this event's stores
                    nl   = pinv[lab1];
                }
                // branchless swap (r==lab => same-value rewrite, no-op)
                pinv[r]   = pl;
                pinv[lab] = pr;
                // patch both prefetches against this event's two stores
                int rn = nm;
                if (m1 == r)     rn = pl;
                if (m1 == lab)   rn = pr;
                int pln = nl;
                if (lab1 == r)   pln = pl;
                if (lab1 == lab) pln = pr;
                m = m1; lab = lab1; r = rn; pl = pln;
            }
        }
    }
    __syncthreads();

    if (t < LBL) g_idx[t] = pinv[t];   // store pinv directly (scatter gather)
}

// ---------------------------------------------------------------------------
// K3: out[n, pinv[k]] = in[n, k]  (equivalent to out[n,j] = in[n, idx[j]]).
// One warp per row; stage permuted via scalar STS (issue-only), coalesced
// float4 LDS, streaming float4 STG (__stcs — output has no reuse).
// ---------------------------------------------------------------------------
__global__ __launch_bounds__(256) void k_gather(const float* __restrict__ in,
                                                float* __restrict__ out, int N) {
    __shared__ int4  sidx[250];        // pinv, packed
    __shared__ float srow[8][1000];

    int t    = threadIdx.x;
    int wid  = t >> 5;
    int lane = t & 31;

    if (t < 250) sidx[t] = reinterpret_cast<const int4*>(g_idx)[t];

    int row = blockIdx.x * 8 + wid;
    float4 v[8];
    if (row < N) {
        const float4* rp = reinterpret_cast<const float4*>(in + (size_t)row * 1000);
#pragma unroll
        for (int it = 0; it < 8; ++it) {
            int k = lane + it * 32;
            if (k < 250) v[it] = rp[k];
        }
    }
    __syncthreads();   // covers sidx (row loads already in flight)

    if (row < N) {
        float* my = &srow[wid][0];
#pragma unroll
        for (int it = 0; it < 8; ++it) {
            int k = lane + it * 32;
            if (k < 250) {
                int4 p = sidx[k];
                my[p.x] = v[it].x;     // permuted scatter into smem
                my[p.y] = v[it].y;
                my[p.z] = v[it].z;
                my[p.w] = v[it].w;
            }
        }
        __syncwarp();
        float4* op = reinterpret_cast<float4*>(out + (size_t)row * 1000);
        const float4* mv = reinterpret_cast<const float4*>(my);
#pragma unroll
        for (int it = 0; it < 8; ++it) {
            int k = lane + it * 32;
            if (k < 250) __stcs(&op[k], mv[k]);   // coalesced streaming write
        }
    }
}

// ---------------------------------------------------------------------------
extern "C" void kernel_launch(void* const* d_in, const int* in_sizes, int n_in,
                              void* d_out, int out_size) {
    const float* in     = (const float*)d_in[0];
    const int*   labels = (const int*)d_in[1];
    float*       out    = (float*)d_out;
    int N = in_sizes[1];   // 32768 rows; L = 1000

    k_first    <<<(N + 255) / 256, 256>>>(labels, N);
    k_argmax_ev<<<(LBL * 32 + 255) / 256, 256>>>(in, N);
    k_scan     <<<1, 1024>>>(N);
    k_gather   <<<(N + 7) / 8, 256>>>(in, out, N);
}

// round 6
// speedup vs baseline: 1.2162x; 1.0538x over previous
#include <cuda_runtime.h>
#include <cuda_bf16.h>

// Problem constants: outputs [64,512,1000] f32, labels [64,512] i32
#define LBL 1000

__device__ __align__(16) int g_first[1024];     // static zero-init; k_scan re-zeros
__device__ __align__(16) int g_argm_ev[1024];   // argmax of each label's first row
__device__ __align__(16) int g_idx[1024];       // pinv (inverse permutation)

// ---------------------------------------------------------------------------
// K0: first occurrence per label, from labels only.
// Encoded as max(N - w) so the empty state is 0 (static zero init, no reset
// kernel; k_scan re-zeros after consuming). 32768 atomics over 1000 addrs.
// ---------------------------------------------------------------------------
__global__ __launch_bounds__(256) void k_first(const int* __restrict__ labels,
                                               int N) {
    int i = blockIdx.x * blockDim.x + threadIdx.x;
    if (i < N) atomicMax(&g_first[labels[i]], N - i);
}

// ---------------------------------------------------------------------------
// K1: argmax of ONLY the first-occurrence rows (<=1000 rows, ~4 MB).
// One warp per label; warp t handles row decode(g_first[t]) if valid.
// ---------------------------------------------------------------------------
__global__ __launch_bounds__(256) void k_argmax_ev(const float* __restrict__ in,
                                                   int N) {
    int t    = (blockIdx.x * blockDim.x + threadIdx.x) >> 5;   // label id
    int lane = threadIdx.x & 31;
    if (t >= LBL) return;
    int enc = g_first[t];
    if (enc <= 0) return;            // label never occurs
    int row = N - enc;               // first-occurrence row

    const float4* rp = reinterpret_cast<const float4*>(in) + (size_t)row * 250;
    float bv = -3.402823466e38f;
    int   bi = 0;
#pragma unroll
    for (int it = 0; it < 7; ++it) {             // k = lane + 32*it <= 223
        int k = lane + it * 32;
        float4 v = rp[k];
        int b = k * 4;
        if (v.x > bv) { bv = v.x; bi = b;     }
        if (v.y > bv) { bv = v.y; bi = b + 1; }
        if (v.z > bv) { bv = v.z; bi = b + 2; }
        if (v.w > bv) { bv = v.w; bi = b + 3; }
    }
    if (lane < 26) {                              // tail: k = lane + 224 < 250
        int k = lane + 224;
        float4 v = rp[k];
        int b = k * 4;
        if (v.x > bv) { bv = v.x; bi = b;     }
        if (v.y > bv) { bv = v.y; bi = b + 1; }
        if (v.z > bv) { bv = v.z; bi = b + 2; }
        if (v.w > bv) { bv = v.w; bi = b + 3; }
    }
#pragma unroll
    for (int off = 16; off > 0; off >>= 1) {
        float ov = __shfl_down_sync(0xFFFFFFFFu, bv, off);
        int   oi = __shfl_down_sync(0xFFFFFFFFu, bi, off);
        if (ov > bv || (ov == bv && oi < bi)) { bv = ov; bi = oi; }
    }
    if (lane == 0) g_argm_ev[t] = bi;
}

// ---------------------------------------------------------------------------
// K2: single block.
//   Phase A: rank events (first occurrences) by row via 32768-bit bitmap +
//            1024-word popc prefix-sum. Self-resets g_first for next replay.
//   Phase B: serial scan, depth-1 software pipeline:
//     Event e: r=pinv[m]; swap(pinv[r],pinv[lab]) i.e. pinv[r]<-pl, pinv[lab]<-pr.
//     * pl-store applied immediately (operands ready early).
//     * pr-store DEFERRED 2 iterations (its data pr is a dependent 29-cyc load;
//       deferral keeps stores from stalling issue).
//     * loads for event e+1 issued right after the pl-store =>
//         - pl_{e+1} = nl needs NO patch (labels distinct across events;
//           lab cells only written by pr-stores of OTHER labels: impossible).
//         - r_{e+1} = nm patched only vs the 2 pending pr-stores:
//           conditions m1==lab_e / lab_{e-1} are register compares.
//     * pr_e = pinv[r_e] read pre-pl-store, patched vs pending pr-store e-1.
//     Chain per event: 1 LDS + 2 SEL ~ 38 cyc (was ~65).
//   Output: g_idx = pinv directly (gather scatters with pinv).
// ---------------------------------------------------------------------------
__global__ __launch_bounds__(1024) void k_scan(int N) {
    __shared__ unsigned  sbit[1024];   // 32768-bit row bitmap
    __shared__ int       sexc[1024];   // exclusive popc prefix per word
    __shared__ long long ev[1024];     // packed (m << 32) | lab, sorted by row
    __shared__ int       pinv[1024];
    __shared__ int       wsum[32];
    __shared__ int       sE;

    int t = threadIdx.x;
    int lane = t & 31, w = t >> 5;

    sbit[t] = 0u;
    pinv[t] = t;
    int enc = (t < LBL) ? g_first[t] : 0;
    g_first[t] = 0;                    // reset for next graph replay
    int myf = (enc > 0) ? (N - enc) : -1;
    __syncthreads();

    if (myf >= 0)
        atomicOr(&sbit[myf >> 5], 1u << (myf & 31));
    __syncthreads();

    // block prefix-sum of per-word popcounts
    unsigned word = sbit[t];
    int c = __popc(word);
    int x = c;
#pragma unroll
    for (int o = 1; o < 32; o <<= 1) {
        int y = __shfl_up_sync(0xFFFFFFFFu, x, o);
        if (lane >= o) x += y;
    }
    if (lane == 31) wsum[w] = x;
    __syncthreads();
    if (t < 32) {
        int v = wsum[t];
        int iv = v;
#pragma unroll
        for (int o = 1; o < 32; o <<= 1) {
            int y = __shfl_up_sync(0xFFFFFFFFu, iv, o);
            if (t >= o) iv += y;
        }
        wsum[t] = iv - v;          // exclusive warp offset
        if (t == 31) sE = iv;      // total number of events
    }
    __syncthreads();
    sexc[t] = wsum[w] + (x - c);
    __syncthreads();

    if (myf >= 0) {
        unsigned wv = sbit[myf >> 5];
        int rank = sexc[myf >> 5] + __popc(wv & ((1u << (myf & 31)) - 1u));
        ev[rank] = ((long long)g_argm_ev[t] << 32) | (unsigned)t;
    }
    __syncthreads();

    // Phase B: depth-1 pipelined serial event loop (thread 0).
    // Cell 1023 (> LBL-1) is a scratch cell for dummy pending stores.
    if (t == 0) {
        int E = sE;
        if (E > 0) {
            ev[E]     = ((long long)1023 << 32) | 1023u;   // pad events
            ev[E + 1] = ((long long)1023 << 32) | 1023u;

            long long e0 = ev[0];
            int m   = (int)(e0 >> 32);
            int lab = (int)(e0 & 0xFFFFFFFFLL);
            int r   = pinv[m];                 // r_0
            int pl  = pinv[lab];               // pl_0
            int labm1 = 1023, labm2 = 1023;    // lab_{e-1}, lab_{e-2} (dummies)
            int prm1  = 1023, prm2  = 1023;    // pr_{e-1}, pr_{e-2}  (dummies)

            for (int e = 0; e < E; ++e) {
                long long e1 = ev[e + 1];
                int m1   = (int)(e1 >> 32);
                int lab1 = (int)(e1 & 0xFFFFFFFFLL);

                pinv[labm2] = prm2;        // deferred pr-store of event e-2
                int prl = pinv[r];         // pre-event value of cell r (pr_e raw)
                pinv[r] = pl;              // immediate pl-store of event e
                int nm = pinv[m1];         // sees pl-stores <= e, pr-stores <= e-2
                int nl = pinv[lab1];       // NO patch needed (labels distinct)

                int pr = (r == labm1) ? prm1 : prl;              // pr_e
                int r1 = (m1 == lab)   ? pr
                       : (m1 == labm1) ? prm1 : nm;              // r_{e+1}

                labm2 = labm1; prm2 = prm1;
                labm1 = lab;   prm1 = pr;
                m = m1; lab = lab1; r = r1; pl = nl;
            }
            // flush the two pending pr-stores (events E-2, E-1)
            pinv[labm2] = prm2;
            pinv[labm1] = prm1;
        }
    }
    __syncthreads();

    if (t < LBL) g_idx[t] = pinv[t];   // store pinv directly (scatter gather)
}

// ---------------------------------------------------------------------------
// K3: out[n, pinv[k]] = in[n, k]  (equivalent to out[n,j] = in[n, idx[j]]).
// One warp per row; stage permuted via scalar STS (issue-only), coalesced
// float4 LDS, streaming float4 STG (__stcs — output has no reuse).
// ---------------------------------------------------------------------------
__global__ __launch_bounds__(256) void k_gather(const float* __restrict__ in,
                                                float* __restrict__ out, int N) {
    __shared__ int4  sidx[250];        // pinv, packed
    __shared__ float srow[8][1000];

    int t    = threadIdx.x;
    int wid  = t >> 5;
    int lane = t & 31;

    if (t < 250) sidx[t] = reinterpret_cast<const int4*>(g_idx)[t];

    int row = blockIdx.x * 8 + wid;
    float4 v[8];
    if (row < N) {
        const float4* rp = reinterpret_cast<const float4*>(in + (size_t)row * 1000);
#pragma unroll
        for (int it = 0; it < 8; ++it) {
            int k = lane + it * 32;
            if (k < 250) v[it] = rp[k];
        }
    }
    __syncthreads();   // covers sidx (row loads already in flight)

    if (row < N) {
        float* my = &srow[wid][0];
#pragma unroll
        for (int it = 0; it < 8; ++it) {
            int k = lane + it * 32;
            if (k < 250) {
                int4 p = sidx[k];
                my[p.x] = v[it].x;     // permuted scatter into smem
                my[p.y] = v[it].y;
                my[p.z] = v[it].z;
                my[p.w] = v[it].w;
            }
        }
        __syncwarp();
        float4* op = reinterpret_cast<float4*>(out + (size_t)row * 1000);
        const float4* mv = reinterpret_cast<const float4*>(my);
#pragma unroll
        for (int it = 0; it < 8; ++it) {
            int k = lane + it * 32;
            if (k < 250) __stcs(&op[k], mv[k]);   // coalesced streaming write
        }
    }
}

// ---------------------------------------------------------------------------
extern "C" void kernel_launch(void* const* d_in, const int* in_sizes, int n_in,
                              void* d_out, int out_size) {
    const float* in     = (const float*)d_in[0];
    const int*   labels = (const int*)d_in[1];
    float*       out    = (float*)d_out;
    int N = in_sizes[1];   // 32768 rows; L = 1000

    k_first    <<<(N + 255) / 256, 256>>>(labels, N);
    k_argmax_ev<<<(LBL * 32 + 255) / 256, 256>>>(in, N);
    k_scan     <<<1, 1024>>>(N);
    k_gather   <<<(N + 7) / 8, 256>>>(in, out, N);
}

// round 7
// speedup vs baseline: 1.5866x; 1.3046x over previous
#include <cuda_runtime.h>
#include <cuda_bf16.h>

// Problem constants: outputs [64,512,1000] f32, labels [64,512] i32
#define LBL 1000

__device__ __align__(16) int g_first[1024];     // static zero-init; k_scan re-zeros
__device__ __align__(16) int g_argm_ev[1024];   // argmax of each label's first row
__device__ __align__(16) int g_idx[1024];       // pinv (inverse permutation)

// ---------------------------------------------------------------------------
// K0: first occurrence per label, from labels only.
// Encoded as max(N - w) so the empty state is 0 (static zero init, no reset
// kernel; k_scan re-zeros after consuming). 32768 atomics over 1000 addrs.
// ---------------------------------------------------------------------------
__global__ __launch_bounds__(256) void k_first(const int* __restrict__ labels,
                                               int N) {
    int i = blockIdx.x * blockDim.x + threadIdx.x;
    if (i < N) atomicMax(&g_first[labels[i]], N - i);
}

// ---------------------------------------------------------------------------
// K1: argmax of ONLY the first-occurrence rows (<=1000 rows, ~4 MB).
// One warp per label; warp t handles row decode(g_first[t]) if valid.
// ---------------------------------------------------------------------------
__global__ __launch_bounds__(256) void k_argmax_ev(const float* __restrict__ in,
                                                   int N) {
    int t    = (blockIdx.x * blockDim.x + threadIdx.x) >> 5;   // label id
    int lane = threadIdx.x & 31;
    if (t >= LBL) return;
    int enc = g_first[t];
    if (enc <= 0) return;            // label never occurs
    int row = N - enc;               // first-occurrence row

    const float4* rp = reinterpret_cast<const float4*>(in) + (size_t)row * 250;
    float bv = -3.402823466e38f;
    int   bi = 0;
#pragma unroll
    for (int it = 0; it < 7; ++it) {             // k = lane + 32*it <= 223
        int k = lane + it * 32;
        float4 v = rp[k];
        int b = k * 4;
        if (v.x > bv) { bv = v.x; bi = b;     }
        if (v.y > bv) { bv = v.y; bi = b + 1; }
        if (v.z > bv) { bv = v.z; bi = b + 2; }
        if (v.w > bv) { bv = v.w; bi = b + 3; }
    }
    if (lane < 26) {                              // tail: k = lane + 224 < 250
        int k = lane + 224;
        float4 v = rp[k];
        int b = k * 4;
        if (v.x > bv) { bv = v.x; bi = b;     }
        if (v.y > bv) { bv = v.y; bi = b + 1; }
        if (v.z > bv) { bv = v.z; bi = b + 2; }
        if (v.w > bv) { bv = v.w; bi = b + 3; }
    }
#pragma unroll
    for (int off = 16; off > 0; off >>= 1) {
        float ov = __shfl_down_sync(0xFFFFFFFFu, bv, off);
        int   oi = __shfl_down_sync(0xFFFFFFFFu, bi, off);
        if (ov > bv || (ov == bv && oi < bi)) { bv = ov; bi = oi; }
    }
    if (lane == 0) g_argm_ev[t] = bi;
}

// ---------------------------------------------------------------------------
// K2: single block.
//   Phase A: rank events (first occurrences) by row via 32768-bit bitmap +
//            1024-word popc prefix-sum. Self-resets g_first for next replay.
//   Phase B: WARP-SPECULATIVE batch scan (warp 0).
//     Event e: r=pinv[m]; swap(pinv[r],pinv[lab]).
//       reads {m, lab, r}; writes {r, lab}.
//     Each round: 32 lanes speculatively execute 32 consecutive events on the
//     round-start state; atomicMin lane-stamps on each lane's WRITE cells;
//     lane e is hazardous iff stamp[m|r|lab] < e (an earlier lane writes a
//     cell e touches). Commit the prefix before the first hazard (its swaps
//     provably reproduce serial order: no cell intersections => speculation
//     exact). Lane 0 can never hazard => guaranteed progress.
//     Events >= E are dummies (m=lab=1023, untouched cell => self no-op).
//   Output: g_idx = pinv directly (gather scatters with pinv).
// ---------------------------------------------------------------------------
__global__ __launch_bounds__(1024) void k_scan(int N) {
    __shared__ unsigned  sbit[1024];   // 32768-bit row bitmap
    __shared__ int       sexc[1024];   // exclusive popc prefix per word
    __shared__ long long ev[1088];     // packed (m << 32) | lab, sorted by row
    __shared__ int       pinv[1024];
    __shared__ int       stamp[1024];  // per-cell lane stamps for hazard detect
    __shared__ int       wsum[32];
    __shared__ int       sE;

    int t = threadIdx.x;
    int lane = t & 31, w = t >> 5;

    sbit[t]  = 0u;
    pinv[t]  = t;
    stamp[t] = 63;
    ev[t]    = ((long long)1023 << 32) | 1023u;     // dummy everywhere
    if (t < 64) ev[1024 + t] = ((long long)1023 << 32) | 1023u;
    int enc = (t < LBL) ? g_first[t] : 0;
    g_first[t] = 0;                    // reset for next graph replay
    int myf = (enc > 0) ? (N - enc) : -1;
    __syncthreads();

    if (myf >= 0)
        atomicOr(&sbit[myf >> 5], 1u << (myf & 31));
    __syncthreads();

    // block prefix-sum of per-word popcounts
    unsigned word = sbit[t];
    int c = __popc(word);
    int x = c;
#pragma unroll
    for (int o = 1; o < 32; o <<= 1) {
        int y = __shfl_up_sync(0xFFFFFFFFu, x, o);
        if (lane >= o) x += y;
    }
    if (lane == 31) wsum[w] = x;
    __syncthreads();
    if (t < 32) {
        int v = wsum[t];
        int iv = v;
#pragma unroll
        for (int o = 1; o < 32; o <<= 1) {
            int y = __shfl_up_sync(0xFFFFFFFFu, iv, o);
            if (t >= o) iv += y;
        }
        wsum[t] = iv - v;          // exclusive warp offset
        if (t == 31) sE = iv;      // total number of events
    }
    __syncthreads();
    sexc[t] = wsum[w] + (x - c);
    __syncthreads();

    if (myf >= 0) {
        unsigned wv = sbit[myf >> 5];
        int rank = sexc[myf >> 5] + __popc(wv & ((1u << (myf & 31)) - 1u));
        ev[rank] = ((long long)g_argm_ev[t] << 32) | (unsigned)t;
    }
    __syncthreads();

    // Phase B: warp-speculative batch loop (warp 0 only)
    if (t < 32) {
        const unsigned FULL = 0xFFFFFFFFu;
        int E = sE;
        int base = 0;
        while (base < E) {
            long long ee = ev[base + lane];
            int m   = (int)(ee >> 32);
            int lab = (int)(ee & 0xFFFFFFFFLL);
            int r   = pinv[m];                // speculative (round-start state)
            int pl  = pinv[lab];
            int pr  = pinv[r];
            atomicMin(&stamp[r],   lane);
            atomicMin(&stamp[lab], lane);
            __syncwarp(FULL);
            int hz = (stamp[m] < lane) | (stamp[r] < lane) | (stamp[lab] < lane);
            unsigned bal = __ballot_sync(FULL, hz);
            int f = bal ? (__ffs(bal) - 1) : 32;    // f >= 1 always (lane 0 safe)
            stamp[r]   = 63;                   // reset stamps (post-ballot sync)
            stamp[lab] = 63;
            if (lane < f) {                    // commit conflict-free prefix
                pinv[r]   = pl;
                pinv[lab] = pr;
            }
            __syncwarp(FULL);
            base += f;
        }
    }
    __syncthreads();

    if (t < LBL) g_idx[t] = pinv[t];   // store pinv directly (scatter gather)
}

// ---------------------------------------------------------------------------
// K3: out[n, pinv[k]] = in[n, k]  (equivalent to out[n,j] = in[n, idx[j]]).
// One warp per row; stage permuted via scalar STS (issue-only), coalesced
// float4 LDS, streaming float4 STG (__stcs — output has no reuse).
// ---------------------------------------------------------------------------
__global__ __launch_bounds__(256) void k_gather(const float* __restrict__ in,
                                                float* __restrict__ out, int N) {
    __shared__ int4  sidx[250];        // pinv, packed
    __shared__ float srow[8][1000];

    int t    = threadIdx.x;
    int wid  = t >> 5;
    int lane = t & 31;

    if (t < 250) sidx[t] = reinterpret_cast<const int4*>(g_idx)[t];

    int row = blockIdx.x * 8 + wid;
    float4 v[8];
    if (row < N) {
        const float4* rp = reinterpret_cast<const float4*>(in + (size_t)row * 1000);
#pragma unroll
        for (int it = 0; it < 8; ++it) {
            int k = lane + it * 32;
            if (k < 250) v[it] = rp[k];
        }
    }
    __syncthreads();   // covers sidx (row loads already in flight)

    if (row < N) {
        float* my = &srow[wid][0];
#pragma unroll
        for (int it = 0; it < 8; ++it) {
            int k = lane + it * 32;
            if (k < 250) {
                int4 p = sidx[k];
                my[p.x] = v[it].x;     // permuted scatter into smem
                my[p.y] = v[it].y;
                my[p.z] = v[it].z;
                my[p.w] = v[it].w;
            }
        }
        __syncwarp();
        float4* op = reinterpret_cast<float4*>(out + (size_t)row * 1000);
        const float4* mv = reinterpret_cast<const float4*>(my);
#pragma unroll
        for (int it = 0; it < 8; ++it) {
            int k = lane + it * 32;
            if (k < 250) __stcs(&op[k], mv[k]);   // coalesced streaming write
        }
    }
}

// ---------------------------------------------------------------------------
extern "C" void kernel_launch(void* const* d_in, const int* in_sizes, int n_in,
                              void* d_out, int out_size) {
    const float* in     = (const float*)d_in[0];
    const int*   labels = (const int*)d_in[1];
    float*       out    = (float*)d_out;
    int N = in_sizes[1];   // 32768 rows; L = 1000

    k_first    <<<(N + 255) / 256, 256>>>(labels, N);
    k_argmax_ev<<<(LBL * 32 + 255) / 256, 256>>>(in, N);
    k_scan     <<<1, 1024>>>(N);
    k_gather   <<<(N + 7) / 8, 256>>>(in, out, N);
}